// round 1
// baseline (speedup 1.0000x reference)
#include <cuda_runtime.h>
#include <math.h>

#define Bb   128
#define Ss   1024
#define IND  256
#define MM   64
#define DD   128
#define OUTD 128
#define ROWS (Bb*Ss)   // 131072

// ---------------- scratch (device globals; no allocation allowed) ----------------
__device__ __align__(16) float g_Wk2[IND*MM];            // Wr @ Mk^T  (256 x 64)
__device__ __align__(16) float g_bk2[MM];
__device__ __align__(16) float g_w[(size_t)ROWS*MM];     // softmax weights  33.5MB
__device__ __align__(16) float g_e[(size_t)ROWS*DD];     // sigmoid(v)       67MB
__device__ __align__(16) float g_a[(size_t)ROWS*DD];     // tanh(v)          67MB
__device__ __align__(16) float g_r[(size_t)ROWS*DD];     // read vectors     67MB

// ---------------- K0: fold Wr into memory_key ----------------
__global__ void k0_fold(const float* __restrict__ Wr, const float* __restrict__ br,
                        const float* __restrict__ Mk) {
    int gid = blockIdx.x * 256 + threadIdx.x;
    if (gid < IND*MM) {
        int i = gid >> 6, m = gid & 63;
        const float* wr = Wr + (size_t)i * DD;
        const float* mk = Mk + (size_t)m * DD;
        float s = 0.f;
        #pragma unroll 8
        for (int d = 0; d < DD; d++) s = fmaf(wr[d], mk[d], s);
        g_Wk2[i*MM + m] = s;
    } else if (gid < IND*MM + MM) {
        int m = gid - IND*MM;
        const float* mk = Mk + (size_t)m * DD;
        float s = 0.f;
        #pragma unroll 8
        for (int d = 0; d < DD; d++) s = fmaf(br[d], mk[d], s);
        g_bk2[m] = s;
    }
}

// ---------------- K1a: w = softmax(x @ Wk2 + bk2), rows tiled 128, N=64 ----------------
__global__ __launch_bounds__(256) void k1a_wsoftmax(const float* __restrict__ x) {
    __shared__ float As[16][128];
    __shared__ float Bs[16][64];
    __shared__ float sC[128][65];
    __shared__ float rmax[128], rinv[128];

    int tid = threadIdx.x;
    int tx = tid & 15;          // col group (4 cols)
    int ty = tid >> 4;          // row group (8 rows)
    int rowBase = blockIdx.x * 128;

    float acc[8][4];
    #pragma unroll
    for (int i = 0; i < 8; i++)
        #pragma unroll
        for (int j = 0; j < 4; j++) acc[i][j] = 0.f;

    for (int kb = 0; kb < IND; kb += 16) {
        // A tile: 128 rows x 16 k  -> As[k][row]
        #pragma unroll
        for (int it = 0; it < 2; it++) {
            int f4 = tid + it * 256;
            int row = f4 >> 2, kk4 = f4 & 3;
            float4 v = *(const float4*)(x + (size_t)(rowBase + row) * IND + kb + kk4 * 4);
            As[kk4*4+0][row] = v.x; As[kk4*4+1][row] = v.y;
            As[kk4*4+2][row] = v.z; As[kk4*4+3][row] = v.w;
        }
        // B tile: 16 k x 64 n
        {
            int k = tid >> 4, n4 = tid & 15;
            *(float4*)&Bs[k][n4*4] = *(const float4*)(g_Wk2 + (size_t)(kb + k) * MM + n4 * 4);
        }
        __syncthreads();
        #pragma unroll
        for (int k = 0; k < 16; k++) {
            float ra[8], rb[4];
            #pragma unroll
            for (int i = 0; i < 8; i++) ra[i] = As[k][ty*8 + i];
            #pragma unroll
            for (int j = 0; j < 4; j++) rb[j] = Bs[k][tx*4 + j];
            #pragma unroll
            for (int i = 0; i < 8; i++)
                #pragma unroll
                for (int j = 0; j < 4; j++) acc[i][j] = fmaf(ra[i], rb[j], acc[i][j]);
        }
        __syncthreads();
    }
    // bias + stage logits
    #pragma unroll
    for (int i = 0; i < 8; i++)
        #pragma unroll
        for (int j = 0; j < 4; j++) {
            float v = acc[i][j] + g_bk2[tx*4 + j];
            acc[i][j] = v;
            sC[ty*8 + i][tx*4 + j] = v;
        }
    __syncthreads();
    // softmax stats: one lane-pair per row
    {
        int row = tid >> 1, h = tid & 1;
        float mx = -1e30f;
        #pragma unroll 8
        for (int i = 0; i < 32; i++) mx = fmaxf(mx, sC[row][h*32 + i]);
        mx = fmaxf(mx, __shfl_xor_sync(0xffffffffu, mx, 1));
        float s = 0.f;
        #pragma unroll 8
        for (int i = 0; i < 32; i++) s += expf(sC[row][h*32 + i] - mx);
        s += __shfl_xor_sync(0xffffffffu, s, 1);
        if (!h) { rmax[row] = mx; rinv[row] = 1.f / s; }
    }
    __syncthreads();
    // normalized write (coalesced float4)
    #pragma unroll
    for (int i = 0; i < 8; i++) {
        int row = ty*8 + i;
        float m = rmax[row], inv = rinv[row];
        float4 wv;
        wv.x = expf(acc[i][0] - m) * inv;
        wv.y = expf(acc[i][1] - m) * inv;
        wv.z = expf(acc[i][2] - m) * inv;
        wv.w = expf(acc[i][3] - m) * inv;
        *(float4*)(g_w + (size_t)(rowBase + row) * MM + tx * 4) = wv;
    }
}

// ---------------- K1b: v = x @ Ww + bw ; e=sigmoid(v), a=tanh(v) ----------------
__global__ __launch_bounds__(256) void k1b_ea(const float* __restrict__ x,
                                              const float* __restrict__ Ww,
                                              const float* __restrict__ bw) {
    __shared__ float As[16][128];
    __shared__ float Bs[16][128];
    int tid = threadIdx.x;
    int tx = tid & 15;          // col group (8 cols)
    int ty = tid >> 4;          // row group (8 rows)
    int rowBase = blockIdx.x * 128;

    float acc[8][8];
    #pragma unroll
    for (int i = 0; i < 8; i++)
        #pragma unroll
        for (int j = 0; j < 8; j++) acc[i][j] = 0.f;

    for (int kb = 0; kb < IND; kb += 16) {
        #pragma unroll
        for (int it = 0; it < 2; it++) {
            int f4 = tid + it * 256;
            int row = f4 >> 2, kk4 = f4 & 3;
            float4 v = *(const float4*)(x + (size_t)(rowBase + row) * IND + kb + kk4 * 4);
            As[kk4*4+0][row] = v.x; As[kk4*4+1][row] = v.y;
            As[kk4*4+2][row] = v.z; As[kk4*4+3][row] = v.w;
        }
        #pragma unroll
        for (int it = 0; it < 2; it++) {
            int f4 = tid + it * 256;
            int k = f4 >> 5, n4 = f4 & 31;
            *(float4*)&Bs[k][n4*4] = *(const float4*)(Ww + (size_t)(kb + k) * DD + n4 * 4);
        }
        __syncthreads();
        #pragma unroll
        for (int k = 0; k < 16; k++) {
            float ra[8], rb[8];
            #pragma unroll
            for (int i = 0; i < 8; i++) ra[i] = As[k][ty*8 + i];
            #pragma unroll
            for (int j = 0; j < 8; j++) rb[j] = Bs[k][tx*8 + j];
            #pragma unroll
            for (int i = 0; i < 8; i++)
                #pragma unroll
                for (int j = 0; j < 8; j++) acc[i][j] = fmaf(ra[i], rb[j], acc[i][j]);
        }
        __syncthreads();
    }
    float bv[8];
    #pragma unroll
    for (int j = 0; j < 8; j++) bv[j] = bw[tx*8 + j];
    #pragma unroll
    for (int i = 0; i < 8; i++) {
        size_t row = (size_t)(rowBase + ty*8 + i);
        #pragma unroll
        for (int jj = 0; jj < 8; jj += 4) {
            float4 ev, av;
            float v0 = acc[i][jj+0] + bv[jj+0];
            float v1 = acc[i][jj+1] + bv[jj+1];
            float v2 = acc[i][jj+2] + bv[jj+2];
            float v3 = acc[i][jj+3] + bv[jj+3];
            ev.x = 1.f/(1.f+expf(-v0)); av.x = tanhf(v0);
            ev.y = 1.f/(1.f+expf(-v1)); av.y = tanhf(v1);
            ev.z = 1.f/(1.f+expf(-v2)); av.z = tanhf(v2);
            ev.w = 1.f/(1.f+expf(-v3)); av.w = tanhf(v3);
            *(float4*)(g_e + row * DD + tx*8 + jj) = ev;
            *(float4*)(g_a + row * DD + tx*8 + jj) = av;
        }
    }
}

// ---------------- K2: sequential scan, one CTA per batch ----------------
// thread: d = tid>>1, owns m in [half*32, half*32+32); Mv in registers
__global__ __launch_bounds__(256) void k2_scan(const float* __restrict__ mv0) {
    int b = blockIdx.x;
    int tid = threadIdx.x;
    int d = tid >> 1, half = tid & 1, mbase = half * 32;

    float Mv[32];
    #pragma unroll
    for (int j = 0; j < 32; j++) Mv[j] = mv0[(size_t)(mbase + j) * DD + d];

    __shared__ float sw[2][64];
    __shared__ float se[2][128];
    __shared__ float sa[2][128];

    const float* wp = g_w + (size_t)b * Ss * MM;
    const float* ep = g_e + (size_t)b * Ss * DD;
    const float* ap = g_a + (size_t)b * Ss * DD;
    float*       rp = g_r + (size_t)b * Ss * DD;

    // prefetch step 0 into buf 0
    {
        int i = tid;
        if (i < 64)        sw[0][i]       = wp[i];
        else if (i < 192)  se[0][i - 64]  = ep[i - 64];
        else               sa[0][i - 192] = ap[i - 192];
        i = tid + 256;
        if (i < 320)       sa[0][i - 192] = ap[i - 192];
    }
    __syncthreads();

    for (int t = 0; t < Ss; t++) {
        int buf = t & 1;
        if (t + 1 < Ss) {
            const float* wn = wp + (size_t)(t + 1) * MM;
            const float* en = ep + (size_t)(t + 1) * DD;
            const float* an = ap + (size_t)(t + 1) * DD;
            int i = tid;
            if (i < 64)        sw[buf^1][i]       = wn[i];
            else if (i < 192)  se[buf^1][i - 64]  = en[i - 64];
            else               sa[buf^1][i - 192] = an[i - 192];
            i = tid + 256;
            if (i < 320)       sa[buf^1][i - 192] = an[i - 192];
        }
        float e = se[buf][d];
        float a = sa[buf][d];
        float wr_[32];
        #pragma unroll
        for (int j = 0; j < 32; j += 4) {
            float4 v = *(const float4*)&sw[buf][mbase + j];
            wr_[j] = v.x; wr_[j+1] = v.y; wr_[j+2] = v.z; wr_[j+3] = v.w;
        }
        float r0 = 0.f, r1 = 0.f, r2 = 0.f, r3 = 0.f;
        #pragma unroll
        for (int j = 0; j < 32; j += 4) {
            float t0 = wr_[j+0] * Mv[j+0]; r0 += t0;
            Mv[j+0] = fmaf(-t0, e, Mv[j+0]); Mv[j+0] = fmaf(wr_[j+0], a, Mv[j+0]);
            float t1 = wr_[j+1] * Mv[j+1]; r1 += t1;
            Mv[j+1] = fmaf(-t1, e, Mv[j+1]); Mv[j+1] = fmaf(wr_[j+1], a, Mv[j+1]);
            float t2 = wr_[j+2] * Mv[j+2]; r2 += t2;
            Mv[j+2] = fmaf(-t2, e, Mv[j+2]); Mv[j+2] = fmaf(wr_[j+2], a, Mv[j+2]);
            float t3 = wr_[j+3] * Mv[j+3]; r3 += t3;
            Mv[j+3] = fmaf(-t3, e, Mv[j+3]); Mv[j+3] = fmaf(wr_[j+3], a, Mv[j+3]);
        }
        float r = (r0 + r1) + (r2 + r3);
        r += __shfl_xor_sync(0xffffffffu, r, 1);
        if (!half) rp[(size_t)t * DD + d] = r;
        __syncthreads();
    }
}

// ---------------- K3: y = sigmoid(r @ Wp + bp) ----------------
__global__ __launch_bounds__(256) void k3_out(const float* __restrict__ Wp,
                                              const float* __restrict__ bp,
                                              float* __restrict__ out) {
    __shared__ float As[16][128];
    __shared__ float Bs[16][128];
    int tid = threadIdx.x;
    int tx = tid & 15;
    int ty = tid >> 4;
    int rowBase = blockIdx.x * 128;

    float acc[8][8];
    #pragma unroll
    for (int i = 0; i < 8; i++)
        #pragma unroll
        for (int j = 0; j < 8; j++) acc[i][j] = 0.f;

    for (int kb = 0; kb < DD; kb += 16) {
        // A tile from g_r: 128 rows x 16 k (row stride DD=128, 4 float4 per 16k? 16k = 4 float4)
        #pragma unroll
        for (int it = 0; it < 2; it++) {
            int f4 = tid + it * 256;
            int row = f4 >> 2, kk4 = f4 & 3;
            float4 v = *(const float4*)(g_r + (size_t)(rowBase + row) * DD + kb + kk4 * 4);
            As[kk4*4+0][row] = v.x; As[kk4*4+1][row] = v.y;
            As[kk4*4+2][row] = v.z; As[kk4*4+3][row] = v.w;
        }
        #pragma unroll
        for (int it = 0; it < 2; it++) {
            int f4 = tid + it * 256;
            int k = f4 >> 5, n4 = f4 & 31;
            *(float4*)&Bs[k][n4*4] = *(const float4*)(Wp + (size_t)(kb + k) * OUTD + n4 * 4);
        }
        __syncthreads();
        #pragma unroll
        for (int k = 0; k < 16; k++) {
            float ra[8], rb[8];
            #pragma unroll
            for (int i = 0; i < 8; i++) ra[i] = As[k][ty*8 + i];
            #pragma unroll
            for (int j = 0; j < 8; j++) rb[j] = Bs[k][tx*8 + j];
            #pragma unroll
            for (int i = 0; i < 8; i++)
                #pragma unroll
                for (int j = 0; j < 8; j++) acc[i][j] = fmaf(ra[i], rb[j], acc[i][j]);
        }
        __syncthreads();
    }
    float bv[8];
    #pragma unroll
    for (int j = 0; j < 8; j++) bv[j] = bp[tx*8 + j];
    #pragma unroll
    for (int i = 0; i < 8; i++) {
        size_t row = (size_t)(rowBase + ty*8 + i);
        #pragma unroll
        for (int jj = 0; jj < 8; jj += 4) {
            float4 yv;
            yv.x = 1.f/(1.f+expf(-(acc[i][jj+0] + bv[jj+0])));
            yv.y = 1.f/(1.f+expf(-(acc[i][jj+1] + bv[jj+1])));
            yv.z = 1.f/(1.f+expf(-(acc[i][jj+2] + bv[jj+2])));
            yv.w = 1.f/(1.f+expf(-(acc[i][jj+3] + bv[jj+3])));
            *(float4*)(out + row * OUTD + tx*8 + jj) = yv;
        }
    }
}

// ---------------- launch ----------------
extern "C" void kernel_launch(void* const* d_in, const int* in_sizes, int n_in,
                              void* d_out, int out_size) {
    const float* x   = (const float*)d_in[0];
    const float* Mk  = (const float*)d_in[1];
    const float* Mv0 = (const float*)d_in[2];
    const float* Wr  = (const float*)d_in[3];
    const float* br  = (const float*)d_in[4];
    const float* Ww  = (const float*)d_in[5];
    const float* bw  = (const float*)d_in[6];
    const float* Wp  = (const float*)d_in[7];
    const float* bp  = (const float*)d_in[8];
    float* out = (float*)d_out;

    k0_fold<<<65, 256>>>(Wr, br, Mk);
    k1a_wsoftmax<<<ROWS/128, 256>>>(x);
    k1b_ea<<<ROWS/128, 256>>>(x, Ww, bw);
    k2_scan<<<Bb, 256>>>(Mv0);
    k3_out<<<ROWS/128, 256>>>(Wp, bp, out);
}

// round 2
// speedup vs baseline: 1.4095x; 1.4095x over previous
#include <cuda_runtime.h>
#include <math.h>

#define Bb   128
#define Ss   1024
#define IND  256
#define MM   64
#define DD   128
#define OUTD 128
#define ROWS (Bb*Ss)   // 131072

typedef unsigned long long u64;

__device__ __forceinline__ u64 pk2(float lo, float hi) {
    u64 r; asm("mov.b64 %0,{%1,%2};" : "=l"(r) : "f"(lo), "f"(hi)); return r;
}
__device__ __forceinline__ void upk2(float& lo, float& hi, u64 v) {
    asm("mov.b64 {%0,%1},%2;" : "=f"(lo), "=f"(hi) : "l"(v));
}
__device__ __forceinline__ u64 fma2(u64 a, u64 b, u64 c) {
    u64 d; asm("fma.rn.f32x2 %0,%1,%2,%3;" : "=l"(d) : "l"(a), "l"(b), "l"(c)); return d;
}
__device__ __forceinline__ u64 mul2(u64 a, u64 b) {
    u64 d; asm("mul.rn.f32x2 %0,%1,%2;" : "=l"(d) : "l"(a), "l"(b)); return d;
}
__device__ __forceinline__ u64 add2(u64 a, u64 b) {
    u64 d; asm("add.rn.f32x2 %0,%1,%2;" : "=l"(d) : "l"(a), "l"(b)); return d;
}

// ---------------- scratch ----------------
__device__ __align__(16) float g_Wk2[IND*MM];
__device__ __align__(16) float g_bk2[MM];
__device__ __align__(16) float g_w[(size_t)ROWS*MM];
__device__ __align__(16) float g_e[(size_t)ROWS*DD];
__device__ __align__(16) float g_a[(size_t)ROWS*DD];
__device__ __align__(16) float g_r[(size_t)ROWS*DD];

// ---------------- K0: fold Wr into memory_key ----------------
__global__ void k0_fold(const float* __restrict__ Wr, const float* __restrict__ br,
                        const float* __restrict__ Mk) {
    int gid = blockIdx.x * 256 + threadIdx.x;
    if (gid < IND*MM) {
        int i = gid >> 6, m = gid & 63;
        const float* wr = Wr + (size_t)i * DD;
        const float* mk = Mk + (size_t)m * DD;
        float s = 0.f;
        #pragma unroll 8
        for (int d = 0; d < DD; d++) s = fmaf(wr[d], mk[d], s);
        g_Wk2[i*MM + m] = s;
    } else if (gid < IND*MM + MM) {
        int m = gid - IND*MM;
        const float* mk = Mk + (size_t)m * DD;
        float s = 0.f;
        #pragma unroll 8
        for (int d = 0; d < DD; d++) s = fmaf(br[d], mk[d], s);
        g_bk2[m] = s;
    }
}

// ---------------- K1a: w = softmax(x @ Wk2 + bk2); packed-N f32x2 GEMM ----------------
// thread tx (0..15) owns column pairs {tx, tx+16}  -> cols {2tx,2tx+1, 2tx+32,2tx+33}
__global__ __launch_bounds__(256) void k1a_wsoftmax(const float* __restrict__ x) {
    __shared__ float As[16][128];
    __shared__ u64   Bs2[16][32];
    __shared__ float sC[128][65];
    __shared__ float rmax[128], rinv[128];

    int tid = threadIdx.x;
    int tx = tid & 15;
    int ty = tid >> 4;
    int rowBase = blockIdx.x * 128;

    u64 acc2[8][2];
    #pragma unroll
    for (int i = 0; i < 8; i++) { acc2[i][0] = 0ull; acc2[i][1] = 0ull; }

    for (int kb = 0; kb < IND; kb += 16) {
        #pragma unroll
        for (int it = 0; it < 2; it++) {
            int f4 = tid + it * 256;
            int row = f4 >> 2, kk4 = f4 & 3;
            float4 v = *(const float4*)(x + (size_t)(rowBase + row) * IND + kb + kk4 * 4);
            As[kk4*4+0][row] = v.x; As[kk4*4+1][row] = v.y;
            As[kk4*4+2][row] = v.z; As[kk4*4+3][row] = v.w;
        }
        {
            int k = tid >> 4, n4 = tid & 15;
            float4 v = *(const float4*)(g_Wk2 + (size_t)(kb + k) * MM + n4 * 4);
            Bs2[k][n4*2+0] = pk2(v.x, v.y);
            Bs2[k][n4*2+1] = pk2(v.z, v.w);
        }
        __syncthreads();
        #pragma unroll
        for (int k = 0; k < 16; k++) {
            u64 rb0 = Bs2[k][tx];
            u64 rb1 = Bs2[k][tx + 16];
            #pragma unroll
            for (int i = 0; i < 8; i++) {
                float a = As[k][ty*8 + i];
                u64 a2 = pk2(a, a);
                acc2[i][0] = fma2(a2, rb0, acc2[i][0]);
                acc2[i][1] = fma2(a2, rb1, acc2[i][1]);
            }
        }
        __syncthreads();
    }
    // bias + stage logits
    float acc[8][4];
    float b0 = g_bk2[2*tx], b1 = g_bk2[2*tx+1], b2 = g_bk2[2*tx+32], b3 = g_bk2[2*tx+33];
    #pragma unroll
    for (int i = 0; i < 8; i++) {
        float lo, hi;
        upk2(lo, hi, acc2[i][0]);
        acc[i][0] = lo + b0; acc[i][1] = hi + b1;
        upk2(lo, hi, acc2[i][1]);
        acc[i][2] = lo + b2; acc[i][3] = hi + b3;
        int row = ty*8 + i;
        sC[row][2*tx]    = acc[i][0];
        sC[row][2*tx+1]  = acc[i][1];
        sC[row][2*tx+32] = acc[i][2];
        sC[row][2*tx+33] = acc[i][3];
    }
    __syncthreads();
    {
        int row = tid >> 1, h = tid & 1;
        float mx = -1e30f;
        #pragma unroll 8
        for (int i = 0; i < 32; i++) mx = fmaxf(mx, sC[row][h*32 + i]);
        mx = fmaxf(mx, __shfl_xor_sync(0xffffffffu, mx, 1));
        float s = 0.f;
        #pragma unroll 8
        for (int i = 0; i < 32; i++) s += expf(sC[row][h*32 + i] - mx);
        s += __shfl_xor_sync(0xffffffffu, s, 1);
        if (!h) { rmax[row] = mx; rinv[row] = 1.f / s; }
    }
    __syncthreads();
    #pragma unroll
    for (int i = 0; i < 8; i++) {
        int row = ty*8 + i;
        float m = rmax[row], inv = rinv[row];
        float* wr = g_w + (size_t)(rowBase + row) * MM;
        *(u64*)(wr + 2*tx)      = pk2(expf(acc[i][0]-m)*inv, expf(acc[i][1]-m)*inv);
        *(u64*)(wr + 2*tx + 32) = pk2(expf(acc[i][2]-m)*inv, expf(acc[i][3]-m)*inv);
    }
}

// ---------------- K1b: v = x @ Ww + bw ; e=sigmoid(v), a=tanh(v); packed-N ----------------
// thread tx owns column pairs {tx, tx+16, tx+32, tx+48}
__global__ __launch_bounds__(256) void k1b_ea(const float* __restrict__ x,
                                              const float* __restrict__ Ww,
                                              const float* __restrict__ bw) {
    __shared__ float As[16][128];
    __shared__ u64   Bs2[16][64];
    int tid = threadIdx.x;
    int tx = tid & 15;
    int ty = tid >> 4;
    int rowBase = blockIdx.x * 128;

    u64 acc2[8][4];
    #pragma unroll
    for (int i = 0; i < 8; i++)
        #pragma unroll
        for (int j = 0; j < 4; j++) acc2[i][j] = 0ull;

    for (int kb = 0; kb < IND; kb += 16) {
        #pragma unroll
        for (int it = 0; it < 2; it++) {
            int f4 = tid + it * 256;
            int row = f4 >> 2, kk4 = f4 & 3;
            float4 v = *(const float4*)(x + (size_t)(rowBase + row) * IND + kb + kk4 * 4);
            As[kk4*4+0][row] = v.x; As[kk4*4+1][row] = v.y;
            As[kk4*4+2][row] = v.z; As[kk4*4+3][row] = v.w;
        }
        #pragma unroll
        for (int it = 0; it < 2; it++) {
            int f4 = tid + it * 256;
            int k = f4 >> 5, n4 = f4 & 31;
            float4 v = *(const float4*)(Ww + (size_t)(kb + k) * DD + n4 * 4);
            Bs2[k][n4*2+0] = pk2(v.x, v.y);
            Bs2[k][n4*2+1] = pk2(v.z, v.w);
        }
        __syncthreads();
        #pragma unroll
        for (int k = 0; k < 16; k++) {
            u64 rb[4];
            #pragma unroll
            for (int j = 0; j < 4; j++) rb[j] = Bs2[k][tx + 16*j];
            #pragma unroll
            for (int i = 0; i < 8; i++) {
                float a = As[k][ty*8 + i];
                u64 a2 = pk2(a, a);
                #pragma unroll
                for (int j = 0; j < 4; j++) acc2[i][j] = fma2(a2, rb[j], acc2[i][j]);
            }
        }
        __syncthreads();
    }
    float blo[4], bhi[4];
    #pragma unroll
    for (int j = 0; j < 4; j++) {
        int c = 2*(tx + 16*j);
        blo[j] = bw[c]; bhi[j] = bw[c+1];
    }
    #pragma unroll
    for (int i = 0; i < 8; i++) {
        size_t row = (size_t)(rowBase + ty*8 + i);
        #pragma unroll
        for (int j = 0; j < 4; j++) {
            float lo, hi;
            upk2(lo, hi, acc2[i][j]);
            float v0 = lo + blo[j], v1 = hi + bhi[j];
            int c = 2*(tx + 16*j);
            *(u64*)(g_e + row*DD + c) = pk2(1.f/(1.f+expf(-v0)), 1.f/(1.f+expf(-v1)));
            *(u64*)(g_a + row*DD + c) = pk2(tanhf(v0), tanhf(v1));
        }
    }
}

// ---------------- K2: warp-autonomous scan, f32x2, no syncthreads ----------------
// CTA = batch. warp (8/CTA) owns d-range [warp*16, warp*16+16).
// lane: dp = lane&7 -> d-pair (d0 = warp*16 + dp*2), mq = lane>>3 -> m in [mq*16, mq*16+16)
__global__ __launch_bounds__(256) void k2_scan(const float* __restrict__ mv0) {
    int b = blockIdx.x;
    int warp = threadIdx.x >> 5, lane = threadIdx.x & 31;
    int dp = lane & 7, mq = lane >> 3;
    int d0 = warp * 16 + dp * 2;
    int m0 = mq * 16;

    const float* wp = g_w + (size_t)b * Ss * MM;
    const float* ep = g_e + (size_t)b * Ss * DD;
    const float* ap = g_a + (size_t)b * Ss * DD;
    float*       rp = g_r + (size_t)b * Ss * DD;

    u64 Mv[16];
    #pragma unroll
    for (int j = 0; j < 16; j++)
        Mv[j] = *(const u64*)(mv0 + (size_t)(m0 + j) * DD + d0);

    float4 w4[2][4];
    u64 e2v[2], a2v[2];

#define FETCH(T, S) do { \
        const float* wt = wp + (size_t)(T) * MM + m0; \
        w4[S][0] = *(const float4*)(wt + 0); \
        w4[S][1] = *(const float4*)(wt + 4); \
        w4[S][2] = *(const float4*)(wt + 8); \
        w4[S][3] = *(const float4*)(wt + 12); \
        e2v[S] = *(const u64*)(ep + (size_t)(T) * DD + d0); \
        a2v[S] = *(const u64*)(ap + (size_t)(T) * DD + d0); \
    } while (0)

    FETCH(0, 0);
    FETCH(1, 1);

    for (int t = 0; t < Ss; t += 2) {
        #pragma unroll
        for (int s = 0; s < 2; s++) {
            // copy consumed slot to locals
            float wf[16];
            #pragma unroll
            for (int q = 0; q < 4; q++) {
                wf[q*4+0] = w4[s][q].x; wf[q*4+1] = w4[s][q].y;
                wf[q*4+2] = w4[s][q].z; wf[q*4+3] = w4[s][q].w;
            }
            float el, eh;
            upk2(el, eh, e2v[s]);
            u64 eneg2 = pk2(-el, -eh);
            u64 a2c = a2v[s];
            // prefetch t+s+2 into slot s
            if (t + s + 2 < Ss) FETCH(t + s + 2, s);

            u64 racc0 = 0ull, racc1 = 0ull, racc2 = 0ull, racc3 = 0ull;
            #pragma unroll
            for (int j = 0; j < 16; j += 4) {
                u64 w20 = pk2(wf[j+0], wf[j+0]);
                u64 t0  = mul2(w20, Mv[j+0]);
                racc0 = add2(racc0, t0);
                Mv[j+0] = fma2(t0, eneg2, Mv[j+0]);
                Mv[j+0] = fma2(w20, a2c, Mv[j+0]);

                u64 w21 = pk2(wf[j+1], wf[j+1]);
                u64 t1  = mul2(w21, Mv[j+1]);
                racc1 = add2(racc1, t1);
                Mv[j+1] = fma2(t1, eneg2, Mv[j+1]);
                Mv[j+1] = fma2(w21, a2c, Mv[j+1]);

                u64 w22 = pk2(wf[j+2], wf[j+2]);
                u64 t2  = mul2(w22, Mv[j+2]);
                racc2 = add2(racc2, t2);
                Mv[j+2] = fma2(t2, eneg2, Mv[j+2]);
                Mv[j+2] = fma2(w22, a2c, Mv[j+2]);

                u64 w23 = pk2(wf[j+3], wf[j+3]);
                u64 t3  = mul2(w23, Mv[j+3]);
                racc3 = add2(racc3, t3);
                Mv[j+3] = fma2(t3, eneg2, Mv[j+3]);
                Mv[j+3] = fma2(w23, a2c, Mv[j+3]);
            }
            u64 rsum = add2(add2(racc0, racc1), add2(racc2, racc3));
            float r0, r1;
            upk2(r0, r1, rsum);
            r0 += __shfl_xor_sync(0xffffffffu, r0, 8);
            r0 += __shfl_xor_sync(0xffffffffu, r0, 16);
            r1 += __shfl_xor_sync(0xffffffffu, r1, 8);
            r1 += __shfl_xor_sync(0xffffffffu, r1, 16);
            if (mq == 0)
                *(u64*)(rp + (size_t)(t + s) * DD + d0) = pk2(r0, r1);
        }
    }
#undef FETCH
}

// ---------------- K3: y = sigmoid(r @ Wp + bp); packed-N ----------------
__global__ __launch_bounds__(256) void k3_out(const float* __restrict__ Wp,
                                              const float* __restrict__ bp,
                                              float* __restrict__ out) {
    __shared__ float As[16][128];
    __shared__ u64   Bs2[16][64];
    int tid = threadIdx.x;
    int tx = tid & 15;
    int ty = tid >> 4;
    int rowBase = blockIdx.x * 128;

    u64 acc2[8][4];
    #pragma unroll
    for (int i = 0; i < 8; i++)
        #pragma unroll
        for (int j = 0; j < 4; j++) acc2[i][j] = 0ull;

    for (int kb = 0; kb < DD; kb += 16) {
        #pragma unroll
        for (int it = 0; it < 2; it++) {
            int f4 = tid + it * 256;
            int row = f4 >> 2, kk4 = f4 & 3;
            float4 v = *(const float4*)(g_r + (size_t)(rowBase + row) * DD + kb + kk4 * 4);
            As[kk4*4+0][row] = v.x; As[kk4*4+1][row] = v.y;
            As[kk4*4+2][row] = v.z; As[kk4*4+3][row] = v.w;
        }
        #pragma unroll
        for (int it = 0; it < 2; it++) {
            int f4 = tid + it * 256;
            int k = f4 >> 5, n4 = f4 & 31;
            float4 v = *(const float4*)(Wp + (size_t)(kb + k) * OUTD + n4 * 4);
            Bs2[k][n4*2+0] = pk2(v.x, v.y);
            Bs2[k][n4*2+1] = pk2(v.z, v.w);
        }
        __syncthreads();
        #pragma unroll
        for (int k = 0; k < 16; k++) {
            u64 rb[4];
            #pragma unroll
            for (int j = 0; j < 4; j++) rb[j] = Bs2[k][tx + 16*j];
            #pragma unroll
            for (int i = 0; i < 8; i++) {
                float a = As[k][ty*8 + i];
                u64 a2 = pk2(a, a);
                #pragma unroll
                for (int j = 0; j < 4; j++) acc2[i][j] = fma2(a2, rb[j], acc2[i][j]);
            }
        }
        __syncthreads();
    }
    float blo[4], bhi[4];
    #pragma unroll
    for (int j = 0; j < 4; j++) {
        int c = 2*(tx + 16*j);
        blo[j] = bp[c]; bhi[j] = bp[c+1];
    }
    #pragma unroll
    for (int i = 0; i < 8; i++) {
        size_t row = (size_t)(rowBase + ty*8 + i);
        #pragma unroll
        for (int j = 0; j < 4; j++) {
            float lo, hi;
            upk2(lo, hi, acc2[i][j]);
            float v0 = lo + blo[j], v1 = hi + bhi[j];
            int c = 2*(tx + 16*j);
            *(u64*)(out + row*OUTD + c) = pk2(1.f/(1.f+expf(-v0)), 1.f/(1.f+expf(-v1)));
        }
    }
}

// ---------------- launch ----------------
extern "C" void kernel_launch(void* const* d_in, const int* in_sizes, int n_in,
                              void* d_out, int out_size) {
    const float* x   = (const float*)d_in[0];
    const float* Mk  = (const float*)d_in[1];
    const float* Mv0 = (const float*)d_in[2];
    const float* Wr  = (const float*)d_in[3];
    const float* br  = (const float*)d_in[4];
    const float* Ww  = (const float*)d_in[5];
    const float* bw  = (const float*)d_in[6];
    const float* Wp  = (const float*)d_in[7];
    const float* bp  = (const float*)d_in[8];
    float* out = (float*)d_out;

    k0_fold<<<65, 256>>>(Wr, br, Mk);
    k1a_wsoftmax<<<ROWS/128, 256>>>(x);
    k1b_ea<<<ROWS/128, 256>>>(x, Ww, bw);
    k2_scan<<<Bb, 256>>>(Mv0);
    k3_out<<<ROWS/128, 256>>>(Wp, bp, out);
}